// round 11
// baseline (speedup 1.0000x reference)
#include <cuda_runtime.h>
#include <cuda_bf16.h>
#include <cstdint>

#define BATCH 4
#define NTOK  4096
#define KSEL  1024

// ---------------- global scratch ----------------
__device__ __nv_bfloat16 g_q [BATCH * NTOK * 64];   // (b, n, c) bf16, pre-scaled
__device__ __nv_bfloat16 g_kT[BATCH * NTOK * 64];   // (b, m, c) bf16
__device__ __nv_bfloat16 g_v [BATCH * 64 * NTOK];   // (b, c, m) bf16
__device__ __nv_bfloat16 g_sb[BATCH * NTOK * NTOK]; // (b, n, m) bf16 scores
__device__ __nv_bfloat16 g_p [BATCH * NTOK * NTOK]; // (b, n, m) bf16 probabilities
__device__ float         g_o [BATCH * NTOK * 64];   // (b, n, c) fp32

__device__ __forceinline__ uint32_t smem_u32(const void* p) {
    uint32_t a;
    asm("{ .reg .u64 t; cvta.to.shared.u64 t, %1; cvt.u32.u64 %0, t; }" : "=r"(a) : "l"(p));
    return a;
}
__device__ __forceinline__ unsigned pack_bf16x2(float hi, float lo) {
    unsigned r;
    asm("cvt.rn.bf16x2.f32 %0, %1, %2;" : "=r"(r) : "f"(hi), "f"(lo));
    return r;
}
#define SWZ(row, chunkByte) ((chunkByte) ^ (((row) & 7) << 4))

__device__ __forceinline__ void cp16(uint32_t saddr, const void* gaddr) {
    asm volatile("cp.async.cg.shared.global [%0], [%1], 16;" :: "r"(saddr), "l"(gaddr));
}
#define CP_COMMIT() asm volatile("cp.async.commit_group;" ::: "memory")
#define CP_WAIT(n)  asm volatile("cp.async.wait_group %0;" :: "n"(n) : "memory")

__device__ __forceinline__ void ldm_x4(uint32_t* a, uint32_t addr) {
    asm volatile("ldmatrix.sync.aligned.m8n8.x4.shared.b16 {%0,%1,%2,%3}, [%4];"
                 : "=r"(a[0]), "=r"(a[1]), "=r"(a[2]), "=r"(a[3]) : "r"(addr));
}
__device__ __forceinline__ void ldm_x2(uint32_t* b, uint32_t addr) {
    asm volatile("ldmatrix.sync.aligned.m8n8.x2.shared.b16 {%0,%1}, [%2];"
                 : "=r"(b[0]), "=r"(b[1]) : "r"(addr));
}
__device__ __forceinline__ void mma_bf16(float* c, const uint32_t* a, const uint32_t* b) {
    asm volatile("mma.sync.aligned.m16n8k16.row.col.f32.bf16.bf16.f32 "
                 "{%0,%1,%2,%3}, {%4,%5,%6,%7}, {%8,%9}, {%0,%1,%2,%3};"
                 : "+f"(c[0]), "+f"(c[1]), "+f"(c[2]), "+f"(c[3])
                 : "r"(a[0]), "r"(a[1]), "r"(a[2]), "r"(a[3]), "r"(b[0]), "r"(b[1]));
}

// ---------------- kernel 1: fused QKV projection ----------------
__global__ __launch_bounds__(256) void qkv_kernel(const float* __restrict__ x,
                                                  const float* __restrict__ skip,
                                                  const float* __restrict__ w_qkv)
{
    __shared__ float sx[64][64];
    __shared__ float ss[64][64];
    const int b  = blockIdx.y;
    const int n0 = blockIdx.x * 64;
    const int t  = threadIdx.x;

    for (int idx = t; idx < 64 * 64; idx += 256) {
        int c = idx >> 6, j = idx & 63;
        sx[c][j] = x[((b * 64 + c) << 12) + n0 + j];
        ss[c][j] = skip[((b * 64 + c) << 12) + n0 + j];
    }
    __syncthreads();

    const float scale = 0.125f;
    for (int r = 0; r < 48; r++) {
        int outIdx = t + (r << 8);
        int sel = outIdx >> 12;
        int rem = outIdx & 4095;
        int o = rem >> 6, j = rem & 63;
        const float* wrow = w_qkv + ((sel << 6) + o) * 64;
        float acc = 0.f;
        if (sel == 0) {
            #pragma unroll
            for (int c = 0; c < 64; c++) acc += wrow[c] * sx[c][j];
            g_q[(size_t)(((b << 12) + n0 + j) << 6) + o] = __float2bfloat16(acc * scale);
        } else {
            #pragma unroll
            for (int c = 0; c < 64; c++) acc += wrow[c] * ss[c][j];
            if (sel == 1) g_kT[(size_t)(((b << 12) + n0 + j) << 6) + o] = __float2bfloat16(acc);
            else          g_v [(size_t)(((b << 6) + o) << 12) + n0 + j] = __float2bfloat16(acc);
        }
    }
}

// ---------------- kernel 2: S = Q K^T -> bf16, 128n x 512m per CTA, cp.async 2-stage ----------------
__global__ __launch_bounds__(256) void scores_mma()
{
    __shared__ __align__(16) char sQ[128 * 128];       // 16 KB
    __shared__ __align__(16) char sK[2][128 * 128];    // 32 KB
    const int b = blockIdx.z, n0 = blockIdx.y * 128, mB = blockIdx.x * 512;
    const int t = threadIdx.x, wid = t >> 5, lane = t & 31;
    const uint32_t sQb = smem_u32(sQ);
    const uint32_t sKb0 = smem_u32(sK[0]);

    #pragma unroll
    for (int k = 0; k < 4; k++) {
        int i = t + k * 256;
        int r = i >> 3, q = i & 7;
        cp16(sQb + r * 128 + SWZ(r, q * 16),
             &g_q[(size_t)((b << 12) + n0 + r) * 64 + q * 8]);
        cp16(sKb0 + r * 128 + SWZ(r, q * 16),
             &g_kT[(size_t)((b << 12) + mB + r) * 64 + q * 8]);
    }
    CP_COMMIT();

    const int wn = wid >> 2, wm = wid & 3;   // warp tile: 64n x 32m
    const int gid = lane >> 2, tc = lane & 3;

    for (int mi = 0; mi < 4; mi++) {
        const uint32_t sKc = sKb0 + (mi & 1) * 16384;
        if (mi < 3) {
            const uint32_t sKn = sKb0 + ((mi + 1) & 1) * 16384;
            const int m0n = mB + (mi + 1) * 128;
            #pragma unroll
            for (int k = 0; k < 4; k++) {
                int i = t + k * 256;
                int r = i >> 3, q = i & 7;
                cp16(sKn + r * 128 + SWZ(r, q * 16),
                     &g_kT[(size_t)((b << 12) + m0n + r) * 64 + q * 8]);
            }
            CP_COMMIT();
            CP_WAIT(1);
        } else {
            CP_WAIT(0);
        }
        __syncthreads();

        float acc[4][4][4];
        #pragma unroll
        for (int i = 0; i < 4; i++)
            #pragma unroll
            for (int j = 0; j < 4; j++)
                #pragma unroll
                for (int e = 0; e < 4; e++) acc[i][j][e] = 0.f;

        #pragma unroll
        for (int ki = 0; ki < 4; ki++) {
            uint32_t afr[4][4], bfr[4][2];
            #pragma unroll
            for (int i = 0; i < 4; i++) {
                int row = wn * 64 + i * 16 + (lane & 15);
                int cb = ki * 32 + (lane >> 4) * 16;
                ldm_x4(afr[i], sQb + row * 128 + SWZ(row, cb));
            }
            #pragma unroll
            for (int j = 0; j < 4; j++) {
                int row = wm * 32 + j * 8 + (lane & 7);
                int cb = ki * 32 + ((lane >> 3) & 1) * 16;
                ldm_x2(bfr[j], sKc + row * 128 + SWZ(row, cb));
            }
            #pragma unroll
            for (int i = 0; i < 4; i++)
                #pragma unroll
                for (int j = 0; j < 4; j++)
                    mma_bf16(acc[i][j], afr[i], bfr[j]);
        }

        const int m0 = mB + mi * 128;
        #pragma unroll
        for (int i = 0; i < 4; i++) {
            int row = n0 + wn * 64 + i * 16 + gid;
            size_t r0 = ((size_t)b << 24) + (size_t)row * NTOK + m0 + wm * 32;
            size_t r1 = r0 + 8 * NTOK;
            #pragma unroll
            for (int j = 0; j < 4; j++) {
                *(unsigned*)&g_sb[r0 + j * 8 + tc * 2] = pack_bf16x2(acc[i][j][1], acc[i][j][0]);
                *(unsigned*)&g_sb[r1 + j * 8 + tc * 2] = pack_bf16x2(acc[i][j][3], acc[i][j][2]);
            }
        }
        __syncthreads();
    }
}

// ---------------- kernel 3: top-k threshold + masked softmax, 512 threads x 8 values ----------------
__global__ __launch_bounds__(512) void select_softmax_kernel()
{
    const int row = blockIdx.x;
    const int b = row >> 12, n = row & 4095;
    const size_t base = ((size_t)b << 24) + (size_t)n * NTOK;
    const int t = threadIdx.x;
    const int wid = t >> 5, lane = t & 31;

    __shared__ int hist16[16][256];   // 16 KB
    __shared__ float candF[4096];     // 16 KB
    __shared__ float warpMax[16], warpMin[16];
    __shared__ int warpTot[8];
    __shared__ int sh_cnt;
    __shared__ int sh_bin, sh_kk;
    __shared__ float sh_thr, sh_z;

    if (t == 0) { sh_cnt = 0; sh_z = 0.f; }
    #pragma unroll
    for (int i = 0; i < 8; i++) ((int*)hist16)[t + i * 512] = 0;

    // load 8 contiguous bf16 per thread (one 16B load)
    float vals[8];
    const size_t myb = base + (size_t)t * 8;
    {
        uint4 raw = *(const uint4*)&g_sb[myb];
        unsigned uw[4] = {raw.x, raw.y, raw.z, raw.w};
        #pragma unroll
        for (int j = 0; j < 4; j++) {
            vals[j * 2 + 0] = __uint_as_float(uw[j] << 16);
            vals[j * 2 + 1] = __uint_as_float(uw[j] & 0xffff0000u);
        }
    }

    float mymax = vals[0], mymin = vals[0];
    #pragma unroll
    for (int i = 1; i < 8; i++) {
        mymax = fmaxf(mymax, vals[i]);
        mymin = fminf(mymin, vals[i]);
    }
    #pragma unroll
    for (int off = 16; off; off >>= 1) {
        mymax = fmaxf(mymax, __shfl_xor_sync(0xffffffffu, mymax, off));
        mymin = fminf(mymin, __shfl_xor_sync(0xffffffffu, mymin, off));
    }
    if (lane == 0) { warpMax[wid] = mymax; warpMin[wid] = mymin; }
    __syncthreads();
    float rmax = warpMax[0], rmin = warpMin[0];
    #pragma unroll
    for (int w = 1; w < 16; w++) {
        rmax = fmaxf(rmax, warpMax[w]);
        rmin = fminf(rmin, warpMin[w]);
    }

    float range = rmax - rmin;
    float scale = 256.0f / (range + 1e-30f) * (1.0f - 1e-6f);
    int* myh = hist16[wid];
    int bins[8];
    #pragma unroll
    for (int i = 0; i < 8; i++) {
        int bin = (int)((vals[i] - rmin) * scale);
        bin = bin < 0 ? 0 : (bin > 255 ? 255 : bin);
        bins[i] = bin;
        atomicAdd(&myh[bin], 1);
    }
    __syncthreads();

    // suffix scan over 256 bins using first 8 warps (t < 256)
    int tot = 0, v = 0;
    if (t < 256) {
        #pragma unroll
        for (int w = 0; w < 16; w++) tot += hist16[w][t];
        v = tot;
        #pragma unroll
        for (int off = 1; off < 32; off <<= 1) {
            int o = __shfl_down_sync(0xffffffffu, v, off);
            if (lane + off < 32) v += o;
        }
        if (lane == 0) warpTot[wid] = v;
    }
    __syncthreads();
    if (t < 256) {
        int above = 0;
        #pragma unroll
        for (int w = 0; w < 8; w++) if (w > wid) above += warpTot[w];
        int cum_incl = v + above, cum_excl = cum_incl - tot;
        if (cum_excl < KSEL && KSEL <= cum_incl) { sh_bin = t; sh_kk = KSEL - cum_excl; }
    }
    __syncthreads();
    const int selbin = sh_bin;
    const int kk = sh_kk;

    {
        int cnt = 0;
        #pragma unroll
        for (int i = 0; i < 8; i++) cnt += (bins[i] == selbin);
        int pos = 0;
        if (cnt) pos = atomicAdd(&sh_cnt, cnt);
        #pragma unroll
        for (int i = 0; i < 8; i++)
            if (bins[i] == selbin) candF[pos++] = vals[i];
    }
    __syncthreads();
    const int ncand = sh_cnt;

    for (int i = t; i < ncand; i += 512) {
        float xx = candF[i];
        int gt = 0, eq = 0;
        for (int j = 0; j < ncand; j++) {
            float y = candF[j];
            gt += (y > xx);
            eq += (y == xx);
        }
        if (gt < kk && kk <= gt + eq) sh_thr = xx;
    }
    __syncthreads();

    const float thr = sh_thr;
    const float M = fmaxf(rmax, 0.f);
    const float expM = __expf(-M);

    // exp only for kept elements; masked contribute the constant expM
    float w[8];
    float zloc = 0.f;
    int nkept = 0;
    #pragma unroll
    for (int i = 0; i < 8; i++) {
        if (vals[i] >= thr) {
            float e = __expf(vals[i] - M);
            w[i] = e;
            zloc += e;
            nkept++;
        } else {
            w[i] = expM;
        }
    }
    zloc += (8 - nkept) * expM;
    #pragma unroll
    for (int off = 16; off; off >>= 1) zloc += __shfl_xor_sync(0xffffffffu, zloc, off);
    if (lane == 0) atomicAdd(&sh_z, zloc);
    __syncthreads();

    float invZ = 1.f / sh_z;
    uint4 o;
    o.x = pack_bf16x2(w[1] * invZ, w[0] * invZ);
    o.y = pack_bf16x2(w[3] * invZ, w[2] * invZ);
    o.z = pack_bf16x2(w[5] * invZ, w[4] * invZ);
    o.w = pack_bf16x2(w[7] * invZ, w[6] * invZ);
    *(uint4*)&g_p[myb] = o;
}

// ---------------- kernel 4: O(n,c) = P V^T, 64n x 64c per CTA, cp.async 4-stage ----------------
__global__ __launch_bounds__(256) void av_mma()
{
    __shared__ __align__(16) char sP[4][64 * 128];   // 32 KB
    __shared__ __align__(16) char sV[4][64 * 128];   // 32 KB
    const int b = blockIdx.y, n0 = blockIdx.x * 64;
    const int t = threadIdx.x, wid = t >> 5, lane = t & 31;
    const uint32_t sPb0 = smem_u32(sP[0]), sVb0 = smem_u32(sV[0]);
    const size_t pb = ((size_t)b << 24);

    // preload chunks 0, 1, 2
    #pragma unroll
    for (int c0 = 0; c0 < 3; c0++) {
        const uint32_t sPn = sPb0 + c0 * 8192;
        const uint32_t sVn = sVb0 + c0 * 8192;
        const int mb = c0 * 64;
        #pragma unroll
        for (int k = 0; k < 2; k++) {
            int i = t + k * 256;
            int r = i >> 3, q = i & 7;
            cp16(sPn + r * 128 + SWZ(r, q * 16),
                 &g_p[pb + (size_t)(n0 + r) * NTOK + mb + q * 8]);
            cp16(sVn + r * 128 + SWZ(r, q * 16),
                 &g_v[(size_t)(((b << 6) + r) << 12) + mb + q * 8]);
        }
        CP_COMMIT();
    }

    const int wn = wid >> 2, wc = wid & 3;   // warp tile: 32n x 16c
    float acc[2][2][4];
    #pragma unroll
    for (int i = 0; i < 2; i++)
        #pragma unroll
        for (int j = 0; j < 2; j++)
            #pragma unroll
            for (int e = 0; e < 4; e++) acc[i][j][e] = 0.f;

    for (int mt = 0; mt < 64; mt++) {
        if (mt < 61) {
            const int mb = (mt + 3) * 64;
            const int nb = (mt + 3) & 3;
            const uint32_t sPn = sPb0 + nb * 8192;
            const uint32_t sVn = sVb0 + nb * 8192;
            #pragma unroll
            for (int k = 0; k < 2; k++) {
                int i = t + k * 256;
                int r = i >> 3, q = i & 7;
                cp16(sPn + r * 128 + SWZ(r, q * 16),
                     &g_p[pb + (size_t)(n0 + r) * NTOK + mb + q * 8]);
                cp16(sVn + r * 128 + SWZ(r, q * 16),
                     &g_v[(size_t)(((b << 6) + r) << 12) + mb + q * 8]);
            }
            CP_COMMIT();
            CP_WAIT(3);
        } else {
            CP_WAIT(0);
        }
        __syncthreads();

        const int cb4 = mt & 3;
        const uint32_t sPc = sPb0 + cb4 * 8192;
        const uint32_t sVc = sVb0 + cb4 * 8192;
        #pragma unroll
        for (int ki = 0; ki < 4; ki++) {
            uint32_t afr[2][4], bfr[2][2];
            #pragma unroll
            for (int i = 0; i < 2; i++) {
                int row = wn * 32 + i * 16 + (lane & 15);
                int cb = ki * 32 + (lane >> 4) * 16;
                ldm_x4(afr[i], sPc + row * 128 + SWZ(row, cb));
            }
            #pragma unroll
            for (int j = 0; j < 2; j++) {
                int row = wc * 16 + j * 8 + (lane & 7);
                int cb = ki * 32 + ((lane >> 3) & 1) * 16;
                ldm_x2(bfr[j], sVc + row * 128 + SWZ(row, cb));
            }
            #pragma unroll
            for (int i = 0; i < 2; i++)
                #pragma unroll
                for (int j = 0; j < 2; j++)
                    mma_bf16(acc[i][j], afr[i], bfr[j]);
        }
        __syncthreads();
    }

    const int gid = lane >> 2, tc = lane & 3;
    #pragma unroll
    for (int i = 0; i < 2; i++) {
        int row = n0 + wn * 32 + i * 16 + gid;
        size_t r0 = (size_t)((b << 12) + row) * 64 + wc * 16;
        size_t r1 = r0 + 8 * 64;
        #pragma unroll
        for (int j = 0; j < 2; j++) {
            *(float2*)&g_o[r0 + j * 8 + tc * 2] = make_float2(acc[i][j][0], acc[i][j][1]);
            *(float2*)&g_o[r1 + j * 8 + tc * 2] = make_float2(acc[i][j][2], acc[i][j][3]);
        }
    }
}

// ---------------- kernel 5: output projection + bias + residual ----------------
__global__ __launch_bounds__(256) void proj_kernel(const float* __restrict__ x,
                                                   const float* __restrict__ w_out,
                                                   const float* __restrict__ b_out,
                                                   const float* __restrict__ gamma,
                                                   float* __restrict__ out)
{
    __shared__ float sT[64][65];
    const int b  = blockIdx.y;
    const int n0 = blockIdx.x * 64;
    const int t  = threadIdx.x;

    for (int idx = t; idx < 64 * 64; idx += 256) {
        int j = idx >> 6, c = idx & 63;
        sT[c][j] = g_o[(size_t)((b << 12) + n0 + j) * 64 + c];
    }
    __syncthreads();

    const float g = gamma[0];
    for (int r = 0; r < 16; r++) {
        int outIdx = t + (r << 8);
        int o = outIdx >> 6, j = outIdx & 63;
        const float* wrow = w_out + o * 64;
        float acc = b_out[o];
        #pragma unroll
        for (int c = 0; c < 64; c++) acc += wrow[c] * sT[c][j];
        size_t gi = (size_t)(((b << 6) + o) << 12) + n0 + j;
        out[gi] = g * acc + x[gi];
    }
}

// ---------------- launch ----------------
extern "C" void kernel_launch(void* const* d_in, const int* in_sizes, int n_in,
                              void* d_out, int out_size)
{
    const float* x     = (const float*)d_in[0];
    const float* skip  = (const float*)d_in[1];
    const float* w_qkv = (const float*)d_in[2];
    const float* w_out = (const float*)d_in[3];
    const float* b_out = (const float*)d_in[4];
    const float* gamma = (const float*)d_in[5];
    float* out = (float*)d_out;

    qkv_kernel<<<dim3(64, BATCH), 256>>>(x, skip, w_qkv);
    scores_mma<<<dim3(8, 32, BATCH), 256>>>();
    select_softmax_kernel<<<BATCH * NTOK, 512>>>();
    av_mma<<<dim3(64, BATCH), 256>>>();
    proj_kernel<<<dim3(64, BATCH), 256>>>(x, w_out, b_out, gamma, out);
}

// round 12
// speedup vs baseline: 1.2614x; 1.2614x over previous
#include <cuda_runtime.h>
#include <cuda_bf16.h>
#include <cstdint>

#define BATCH 4
#define NTOK  4096
#define KSEL  1024

// ---------------- global scratch ----------------
__device__ __nv_bfloat16 g_q [BATCH * NTOK * 64];   // (b, n, c) bf16, pre-scaled
__device__ __nv_bfloat16 g_kT[BATCH * NTOK * 64];   // (b, m, c) bf16
__device__ __nv_bfloat16 g_v [BATCH * 64 * NTOK];   // (b, c, m) bf16
__device__ __nv_bfloat16 g_sb[BATCH * NTOK * NTOK]; // (b, n, m) bf16 scores
__device__ __nv_bfloat16 g_p [BATCH * NTOK * NTOK]; // (b, n, m) bf16 probabilities
__device__ float         g_o [BATCH * NTOK * 64];   // (b, n, c) fp32

__device__ __forceinline__ uint32_t smem_u32(const void* p) {
    uint32_t a;
    asm("{ .reg .u64 t; cvta.to.shared.u64 t, %1; cvt.u32.u64 %0, t; }" : "=r"(a) : "l"(p));
    return a;
}
__device__ __forceinline__ unsigned pack_bf16x2(float hi, float lo) {
    unsigned r;
    asm("cvt.rn.bf16x2.f32 %0, %1, %2;" : "=r"(r) : "f"(hi), "f"(lo));
    return r;
}
#define SWZ(row, chunkByte) ((chunkByte) ^ (((row) & 7) << 4))

__device__ __forceinline__ void cp16(uint32_t saddr, const void* gaddr) {
    asm volatile("cp.async.cg.shared.global [%0], [%1], 16;" :: "r"(saddr), "l"(gaddr));
}
#define CP_COMMIT() asm volatile("cp.async.commit_group;" ::: "memory")
#define CP_WAIT(n)  asm volatile("cp.async.wait_group %0;" :: "n"(n) : "memory")

__device__ __forceinline__ void ldm_x4(uint32_t* a, uint32_t addr) {
    asm volatile("ldmatrix.sync.aligned.m8n8.x4.shared.b16 {%0,%1,%2,%3}, [%4];"
                 : "=r"(a[0]), "=r"(a[1]), "=r"(a[2]), "=r"(a[3]) : "r"(addr));
}
__device__ __forceinline__ void ldm_x2(uint32_t* b, uint32_t addr) {
    asm volatile("ldmatrix.sync.aligned.m8n8.x2.shared.b16 {%0,%1}, [%2];"
                 : "=r"(b[0]), "=r"(b[1]) : "r"(addr));
}
__device__ __forceinline__ void mma_bf16(float* c, const uint32_t* a, const uint32_t* b) {
    asm volatile("mma.sync.aligned.m16n8k16.row.col.f32.bf16.bf16.f32 "
                 "{%0,%1,%2,%3}, {%4,%5,%6,%7}, {%8,%9}, {%0,%1,%2,%3};"
                 : "+f"(c[0]), "+f"(c[1]), "+f"(c[2]), "+f"(c[3])
                 : "r"(a[0]), "r"(a[1]), "r"(a[2]), "r"(a[3]), "r"(b[0]), "r"(b[1]));
}

// ---------------- kernel 0: zero g_o ----------------
__global__ __launch_bounds__(256) void zero_o_kernel()
{
    int i = blockIdx.x * 256 + threadIdx.x;
    ((float4*)g_o)[i] = make_float4(0.f, 0.f, 0.f, 0.f);
}

// ---------------- kernel 1: fused QKV projection ----------------
__global__ __launch_bounds__(256) void qkv_kernel(const float* __restrict__ x,
                                                  const float* __restrict__ skip,
                                                  const float* __restrict__ w_qkv)
{
    __shared__ float sx[64][64];
    __shared__ float ss[64][64];
    const int b  = blockIdx.y;
    const int n0 = blockIdx.x * 64;
    const int t  = threadIdx.x;

    for (int idx = t; idx < 64 * 64; idx += 256) {
        int c = idx >> 6, j = idx & 63;
        sx[c][j] = x[((b * 64 + c) << 12) + n0 + j];
        ss[c][j] = skip[((b * 64 + c) << 12) + n0 + j];
    }
    __syncthreads();

    const float scale = 0.125f;
    for (int r = 0; r < 48; r++) {
        int outIdx = t + (r << 8);
        int sel = outIdx >> 12;
        int rem = outIdx & 4095;
        int o = rem >> 6, j = rem & 63;
        const float* wrow = w_qkv + ((sel << 6) + o) * 64;
        float acc = 0.f;
        if (sel == 0) {
            #pragma unroll
            for (int c = 0; c < 64; c++) acc += wrow[c] * sx[c][j];
            g_q[(size_t)(((b << 12) + n0 + j) << 6) + o] = __float2bfloat16(acc * scale);
        } else {
            #pragma unroll
            for (int c = 0; c < 64; c++) acc += wrow[c] * ss[c][j];
            if (sel == 1) g_kT[(size_t)(((b << 12) + n0 + j) << 6) + o] = __float2bfloat16(acc);
            else          g_v [(size_t)(((b << 6) + o) << 12) + n0 + j] = __float2bfloat16(acc);
        }
    }
}

// ---------------- kernel 2: S = Q K^T -> bf16, 128n x 512m per CTA, cp.async 2-stage ----------------
__global__ __launch_bounds__(256) void scores_mma()
{
    __shared__ __align__(16) char sQ[128 * 128];       // 16 KB
    __shared__ __align__(16) char sK[2][128 * 128];    // 32 KB
    const int b = blockIdx.z, n0 = blockIdx.y * 128, mB = blockIdx.x * 512;
    const int t = threadIdx.x, wid = t >> 5, lane = t & 31;
    const uint32_t sQb = smem_u32(sQ);
    const uint32_t sKb0 = smem_u32(sK[0]);

    #pragma unroll
    for (int k = 0; k < 4; k++) {
        int i = t + k * 256;
        int r = i >> 3, q = i & 7;
        cp16(sQb + r * 128 + SWZ(r, q * 16),
             &g_q[(size_t)((b << 12) + n0 + r) * 64 + q * 8]);
        cp16(sKb0 + r * 128 + SWZ(r, q * 16),
             &g_kT[(size_t)((b << 12) + mB + r) * 64 + q * 8]);
    }
    CP_COMMIT();

    const int wn = wid >> 2, wm = wid & 3;   // warp tile: 64n x 32m
    const int gid = lane >> 2, tc = lane & 3;

    for (int mi = 0; mi < 4; mi++) {
        const uint32_t sKc = sKb0 + (mi & 1) * 16384;
        if (mi < 3) {
            const uint32_t sKn = sKb0 + ((mi + 1) & 1) * 16384;
            const int m0n = mB + (mi + 1) * 128;
            #pragma unroll
            for (int k = 0; k < 4; k++) {
                int i = t + k * 256;
                int r = i >> 3, q = i & 7;
                cp16(sKn + r * 128 + SWZ(r, q * 16),
                     &g_kT[(size_t)((b << 12) + m0n + r) * 64 + q * 8]);
            }
            CP_COMMIT();
            CP_WAIT(1);
        } else {
            CP_WAIT(0);
        }
        __syncthreads();

        float acc[4][4][4];
        #pragma unroll
        for (int i = 0; i < 4; i++)
            #pragma unroll
            for (int j = 0; j < 4; j++)
                #pragma unroll
                for (int e = 0; e < 4; e++) acc[i][j][e] = 0.f;

        #pragma unroll
        for (int ki = 0; ki < 4; ki++) {
            uint32_t afr[4][4], bfr[4][2];
            #pragma unroll
            for (int i = 0; i < 4; i++) {
                int row = wn * 64 + i * 16 + (lane & 15);
                int cb = ki * 32 + (lane >> 4) * 16;
                ldm_x4(afr[i], sQb + row * 128 + SWZ(row, cb));
            }
            #pragma unroll
            for (int j = 0; j < 4; j++) {
                int row = wm * 32 + j * 8 + (lane & 7);
                int cb = ki * 32 + ((lane >> 3) & 1) * 16;
                ldm_x2(bfr[j], sKc + row * 128 + SWZ(row, cb));
            }
            #pragma unroll
            for (int i = 0; i < 4; i++)
                #pragma unroll
                for (int j = 0; j < 4; j++)
                    mma_bf16(acc[i][j], afr[i], bfr[j]);
        }

        const int m0 = mB + mi * 128;
        #pragma unroll
        for (int i = 0; i < 4; i++) {
            int row = n0 + wn * 64 + i * 16 + gid;
            size_t r0 = ((size_t)b << 24) + (size_t)row * NTOK + m0 + wm * 32;
            size_t r1 = r0 + 8 * NTOK;
            #pragma unroll
            for (int j = 0; j < 4; j++) {
                *(unsigned*)&g_sb[r0 + j * 8 + tc * 2] = pack_bf16x2(acc[i][j][1], acc[i][j][0]);
                *(unsigned*)&g_sb[r1 + j * 8 + tc * 2] = pack_bf16x2(acc[i][j][3], acc[i][j][2]);
            }
        }
        __syncthreads();
    }
}

// ---------------- kernel 3: top-k threshold + masked softmax, fixed-range bins ----------------
__global__ __launch_bounds__(256) void select_softmax_kernel()
{
    const int row = blockIdx.x;
    const int b = row >> 12, n = row & 4095;
    const size_t base = ((size_t)b << 24) + (size_t)n * NTOK;
    const int t = threadIdx.x;
    const int wid = t >> 5, lane = t & 31;

    __shared__ int hist8[8][256];
    __shared__ float candF[4096];
    __shared__ float warpMax[8];
    __shared__ int warpTot[8];
    __shared__ int sh_cnt;
    __shared__ int sh_bin, sh_kk;
    __shared__ float sh_thr, sh_z;

    if (t == 0) { sh_cnt = 0; sh_z = 0.f; }
    #pragma unroll
    for (int w = 0; w < 8; w++) hist8[w][t] = 0;

    float vals[16];
    const size_t myb = base + (size_t)t * 16;
    #pragma unroll
    for (int h = 0; h < 2; h++) {
        uint4 raw = *(const uint4*)&g_sb[myb + h * 8];
        unsigned uw[4] = {raw.x, raw.y, raw.z, raw.w};
        #pragma unroll
        for (int j = 0; j < 4; j++) {
            vals[h * 8 + j * 2 + 0] = __uint_as_float(uw[j] << 16);
            vals[h * 8 + j * 2 + 1] = __uint_as_float(uw[j] & 0xffff0000u);
        }
    }

    // row max (for softmax M) + fixed-range binning (scores ~ N(0,1))
    float mymax = vals[0];
    #pragma unroll
    for (int i = 1; i < 16; i++) mymax = fmaxf(mymax, vals[i]);
    #pragma unroll
    for (int off = 16; off; off >>= 1)
        mymax = fmaxf(mymax, __shfl_xor_sync(0xffffffffu, mymax, off));
    if (lane == 0) warpMax[wid] = mymax;

    int* myh = hist8[wid];
    int bins[16];
    #pragma unroll
    for (int i = 0; i < 16; i++) {
        int bin = (int)((vals[i] + 8.0f) * 16.0f);   // fixed range [-8, 8] -> 256 bins
        bin = bin < 0 ? 0 : (bin > 255 ? 255 : bin);
        bins[i] = bin;
        atomicAdd(&myh[bin], 1);
    }
    __syncthreads();

    float rmax = warpMax[0];
    #pragma unroll
    for (int w = 1; w < 8; w++) rmax = fmaxf(rmax, warpMax[w]);

    int tot = 0;
    #pragma unroll
    for (int w = 0; w < 8; w++) tot += hist8[w][t];
    int v = tot;
    #pragma unroll
    for (int off = 1; off < 32; off <<= 1) {
        int o = __shfl_down_sync(0xffffffffu, v, off);
        if (lane + off < 32) v += o;
    }
    if (lane == 0) warpTot[wid] = v;
    __syncthreads();
    int above = 0;
    #pragma unroll
    for (int w = 0; w < 8; w++) if (w > wid) above += warpTot[w];
    int cum_incl = v + above, cum_excl = cum_incl - tot;
    if (cum_excl < KSEL && KSEL <= cum_incl) { sh_bin = t; sh_kk = KSEL - cum_excl; }
    __syncthreads();
    const int selbin = sh_bin;
    const int kk = sh_kk;

    {
        int cnt = 0;
        #pragma unroll
        for (int i = 0; i < 16; i++) cnt += (bins[i] == selbin);
        int pos = 0;
        if (cnt) pos = atomicAdd(&sh_cnt, cnt);
        #pragma unroll
        for (int i = 0; i < 16; i++)
            if (bins[i] == selbin) candF[pos++] = vals[i];
    }
    __syncthreads();
    const int ncand = sh_cnt;

    for (int i = t; i < ncand; i += 256) {
        float xx = candF[i];
        int gt = 0, eq = 0;
        for (int j = 0; j < ncand; j++) {
            float y = candF[j];
            gt += (y > xx);
            eq += (y == xx);
        }
        if (gt < kk && kk <= gt + eq) sh_thr = xx;
    }
    __syncthreads();

    const float thr = sh_thr;
    const float M = fmaxf(rmax, 0.f);
    const float expM = __expf(-M);

    float w[16];
    float zloc = 0.f;
    int nkept = 0;
    #pragma unroll
    for (int i = 0; i < 16; i++) {
        if (vals[i] >= thr) {
            float e = __expf(vals[i] - M);
            w[i] = e;
            zloc += e;
            nkept++;
        } else {
            w[i] = expM;
        }
    }
    zloc += (16 - nkept) * expM;
    #pragma unroll
    for (int off = 16; off; off >>= 1) zloc += __shfl_xor_sync(0xffffffffu, zloc, off);
    if (lane == 0) atomicAdd(&sh_z, zloc);
    __syncthreads();

    float invZ = 1.f / sh_z;
    #pragma unroll
    for (int h = 0; h < 2; h++) {
        uint4 o;
        o.x = pack_bf16x2(w[h*8+1] * invZ, w[h*8+0] * invZ);
        o.y = pack_bf16x2(w[h*8+3] * invZ, w[h*8+2] * invZ);
        o.z = pack_bf16x2(w[h*8+5] * invZ, w[h*8+4] * invZ);
        o.w = pack_bf16x2(w[h*8+7] * invZ, w[h*8+6] * invZ);
        *(uint4*)&g_p[myb + h * 8] = o;
    }
}

// ---------------- kernel 4: O(n,c) = P V^T, 64n x 64c, m-split x2, cp.async 3-stage ----------------
__global__ __launch_bounds__(256) void av_mma()
{
    __shared__ __align__(16) char sP[3][64 * 128];   // 24 KB
    __shared__ __align__(16) char sV[3][64 * 128];   // 24 KB
    const int b = blockIdx.z, n0 = blockIdx.x * 64;
    const int mOff = blockIdx.y * 2048;              // m-split half
    const int t = threadIdx.x, wid = t >> 5, lane = t & 31;
    const uint32_t sPb0 = smem_u32(sP[0]), sVb0 = smem_u32(sV[0]);
    const size_t pb = ((size_t)b << 24);

    // preload chunks 0, 1
    #pragma unroll
    for (int c0 = 0; c0 < 2; c0++) {
        const uint32_t sPn = sPb0 + c0 * 8192;
        const uint32_t sVn = sVb0 + c0 * 8192;
        const int mb = mOff + c0 * 64;
        #pragma unroll
        for (int k = 0; k < 2; k++) {
            int i = t + k * 256;
            int r = i >> 3, q = i & 7;
            cp16(sPn + r * 128 + SWZ(r, q * 16),
                 &g_p[pb + (size_t)(n0 + r) * NTOK + mb + q * 8]);
            cp16(sVn + r * 128 + SWZ(r, q * 16),
                 &g_v[(size_t)(((b << 6) + r) << 12) + mb + q * 8]);
        }
        CP_COMMIT();
    }

    const int wn = wid >> 2, wc = wid & 3;   // warp tile: 32n x 16c
    float acc[2][2][4];
    #pragma unroll
    for (int i = 0; i < 2; i++)
        #pragma unroll
        for (int j = 0; j < 2; j++)
            #pragma unroll
            for (int e = 0; e < 4; e++) acc[i][j][e] = 0.f;

    int cur = 0, nxt = 2;
    for (int mt = 0; mt < 32; mt++) {
        if (mt < 30) {
            const int mb = mOff + (mt + 2) * 64;
            const uint32_t sPn = sPb0 + nxt * 8192;
            const uint32_t sVn = sVb0 + nxt * 8192;
            #pragma unroll
            for (int k = 0; k < 2; k++) {
                int i = t + k * 256;
                int r = i >> 3, q = i & 7;
                cp16(sPn + r * 128 + SWZ(r, q * 16),
                     &g_p[pb + (size_t)(n0 + r) * NTOK + mb + q * 8]);
                cp16(sVn + r * 128 + SWZ(r, q * 16),
                     &g_v[(size_t)(((b << 6) + r) << 12) + mb + q * 8]);
            }
            CP_COMMIT();
            CP_WAIT(2);
            nxt = nxt + 1 == 3 ? 0 : nxt + 1;
        } else {
            CP_WAIT(0);
        }
        __syncthreads();

        const uint32_t sPc = sPb0 + cur * 8192;
        const uint32_t sVc = sVb0 + cur * 8192;
        #pragma unroll
        for (int ki = 0; ki < 4; ki++) {
            uint32_t afr[2][4], bfr[2][2];
            #pragma unroll
            for (int i = 0; i < 2; i++) {
                int row = wn * 32 + i * 16 + (lane & 15);
                int cb = ki * 32 + (lane >> 4) * 16;
                ldm_x4(afr[i], sPc + row * 128 + SWZ(row, cb));
            }
            #pragma unroll
            for (int j = 0; j < 2; j++) {
                int row = wc * 16 + j * 8 + (lane & 7);
                int cb = ki * 32 + ((lane >> 3) & 1) * 16;
                ldm_x2(bfr[j], sVc + row * 128 + SWZ(row, cb));
            }
            #pragma unroll
            for (int i = 0; i < 2; i++)
                #pragma unroll
                for (int j = 0; j < 2; j++)
                    mma_bf16(acc[i][j], afr[i], bfr[j]);
        }
        __syncthreads();
        cur = cur + 1 == 3 ? 0 : cur + 1;
    }

    const int gid = lane >> 2, tc = lane & 3;
    #pragma unroll
    for (int i = 0; i < 2; i++) {
        int row = n0 + wn * 32 + i * 16 + gid;
        size_t r0 = (size_t)((b << 12) + row) * 64 + wc * 16;
        size_t r1 = r0 + 8 * 64;
        #pragma unroll
        for (int j = 0; j < 2; j++) {
            atomicAdd(&g_o[r0 + j * 8 + tc * 2 + 0], acc[i][j][0]);
            atomicAdd(&g_o[r0 + j * 8 + tc * 2 + 1], acc[i][j][1]);
            atomicAdd(&g_o[r1 + j * 8 + tc * 2 + 0], acc[i][j][2]);
            atomicAdd(&g_o[r1 + j * 8 + tc * 2 + 1], acc[i][j][3]);
        }
    }
}

// ---------------- kernel 5: output projection + bias + residual ----------------
__global__ __launch_bounds__(256) void proj_kernel(const float* __restrict__ x,
                                                   const float* __restrict__ w_out,
                                                   const float* __restrict__ b_out,
                                                   const float* __restrict__ gamma,
                                                   float* __restrict__ out)
{
    __shared__ float sT[64][65];
    const int b  = blockIdx.y;
    const int n0 = blockIdx.x * 64;
    const int t  = threadIdx.x;

    for (int idx = t; idx < 64 * 64; idx += 256) {
        int j = idx >> 6, c = idx & 63;
        sT[c][j] = g_o[(size_t)((b << 12) + n0 + j) * 64 + c];
    }
    __syncthreads();

    const float g = gamma[0];
    for (int r = 0; r < 16; r++) {
        int outIdx = t + (r << 8);
        int o = outIdx >> 6, j = outIdx & 63;
        const float* wrow = w_out + o * 64;
        float acc = b_out[o];
        #pragma unroll
        for (int c = 0; c < 64; c++) acc += wrow[c] * sT[c][j];
        size_t gi = (size_t)(((b << 6) + o) << 12) + n0 + j;
        out[gi] = g * acc + x[gi];
    }
}

// ---------------- launch ----------------
extern "C" void kernel_launch(void* const* d_in, const int* in_sizes, int n_in,
                              void* d_out, int out_size)
{
    const float* x     = (const float*)d_in[0];
    const float* skip  = (const float*)d_in[1];
    const float* w_qkv = (const float*)d_in[2];
    const float* w_out = (const float*)d_in[3];
    const float* b_out = (const float*)d_in[4];
    const float* gamma = (const float*)d_in[5];
    float* out = (float*)d_out;

    zero_o_kernel<<<1024, 256>>>();
    qkv_kernel<<<dim3(64, BATCH), 256>>>(x, skip, w_qkv);
    scores_mma<<<dim3(8, 32, BATCH), 256>>>();
    select_softmax_kernel<<<BATCH * NTOK, 256>>>();
    av_mma<<<dim3(64, 2, BATCH), 256>>>();
    proj_kernel<<<dim3(64, BATCH), 256>>>(x, w_out, b_out, gamma, out);
}

// round 13
// speedup vs baseline: 1.4060x; 1.1146x over previous
#include <cuda_runtime.h>
#include <cuda_bf16.h>
#include <cstdint>

#define BATCH 4
#define NTOK  4096
#define KSEL  1024

typedef unsigned long long u64;

// ---------------- global scratch ----------------
__device__ __nv_bfloat16 g_q [BATCH * NTOK * 64];   // (b, n, c) bf16, pre-scaled
__device__ __nv_bfloat16 g_kT[BATCH * NTOK * 64];   // (b, m, c) bf16
__device__ __nv_bfloat16 g_v [BATCH * 64 * NTOK];   // (b, c, m) bf16
__device__ __nv_bfloat16 g_sb[BATCH * NTOK * NTOK]; // (b, n, m) bf16 scores
__device__ __nv_bfloat16 g_p [BATCH * NTOK * NTOK]; // (b, n, m) bf16 probabilities
__device__ float         g_o [BATCH * NTOK * 64];   // (b, n, c) fp32

__device__ __forceinline__ uint32_t smem_u32(const void* p) {
    uint32_t a;
    asm("{ .reg .u64 t; cvta.to.shared.u64 t, %1; cvt.u32.u64 %0, t; }" : "=r"(a) : "l"(p));
    return a;
}
__device__ __forceinline__ unsigned pack_bf16x2(float hi, float lo) {
    unsigned r;
    asm("cvt.rn.bf16x2.f32 %0, %1, %2;" : "=r"(r) : "f"(hi), "f"(lo));
    return r;
}
__device__ __forceinline__ u64 pk(float x, float y) {
    u64 r; asm("mov.b64 %0, {%1, %2};" : "=l"(r) : "f"(x), "f"(y)); return r;
}
__device__ __forceinline__ void fma2(u64& d, u64 a, u64 b) {
    asm("fma.rn.f32x2 %0, %1, %2, %0;" : "+l"(d) : "l"(a), "l"(b));
}
__device__ __forceinline__ void unpk(u64 v, float& lo, float& hi) {
    asm("mov.b64 {%0, %1}, %2;" : "=f"(lo), "=f"(hi) : "l"(v));
}
#define SWZ(row, chunkByte) ((chunkByte) ^ (((row) & 7) << 4))

__device__ __forceinline__ void cp16(uint32_t saddr, const void* gaddr) {
    asm volatile("cp.async.cg.shared.global [%0], [%1], 16;" :: "r"(saddr), "l"(gaddr));
}
#define CP_COMMIT() asm volatile("cp.async.commit_group;" ::: "memory")
#define CP_WAIT(n)  asm volatile("cp.async.wait_group %0;" :: "n"(n) : "memory")

__device__ __forceinline__ void ldm_x4(uint32_t* a, uint32_t addr) {
    asm volatile("ldmatrix.sync.aligned.m8n8.x4.shared.b16 {%0,%1,%2,%3}, [%4];"
                 : "=r"(a[0]), "=r"(a[1]), "=r"(a[2]), "=r"(a[3]) : "r"(addr));
}
__device__ __forceinline__ void ldm_x2(uint32_t* b, uint32_t addr) {
    asm volatile("ldmatrix.sync.aligned.m8n8.x2.shared.b16 {%0,%1}, [%2];"
                 : "=r"(b[0]), "=r"(b[1]) : "r"(addr));
}
__device__ __forceinline__ void mma_bf16(float* c, const uint32_t* a, const uint32_t* b) {
    asm volatile("mma.sync.aligned.m16n8k16.row.col.f32.bf16.bf16.f32 "
                 "{%0,%1,%2,%3}, {%4,%5,%6,%7}, {%8,%9}, {%0,%1,%2,%3};"
                 : "+f"(c[0]), "+f"(c[1]), "+f"(c[2]), "+f"(c[3])
                 : "r"(a[0]), "r"(a[1]), "r"(a[2]), "r"(a[3]), "r"(b[0]), "r"(b[1]));
}

// ---------------- kernel 1: fused QKV projection, f32x2 quads ----------------
__global__ __launch_bounds__(256) void qkv_kernel(const float* __restrict__ x,
                                                  const float* __restrict__ skip,
                                                  const float* __restrict__ w_qkv)
{
    __shared__ float sx[64][64];
    __shared__ float ss[64][64];
    const int b  = blockIdx.y;
    const int n0 = blockIdx.x * 64;
    const int t  = threadIdx.x;

    for (int idx = t; idx < 64 * 64; idx += 256) {
        int c = idx >> 6, j = idx & 63;
        sx[c][j] = x[((b * 64 + c) << 12) + n0 + j];
        ss[c][j] = skip[((b * 64 + c) << 12) + n0 + j];
    }
    __syncthreads();

    #pragma unroll
    for (int r = 0; r < 12; r++) {
        int qi = t + (r << 8);              // quad index, 3072 total
        int sel = qi >> 10;                 // warp-uniform
        int o   = (qi >> 4) & 63;
        int j0  = (qi & 15) << 2;
        const float* wrow = w_qkv + ((sel << 6) + o) * 64;
        const float (*s)[64] = (sel == 0) ? sx : ss;

        u64 acc0 = 0ull, acc1 = 0ull;
        #pragma unroll
        for (int cc = 0; cc < 4; cc++) {
            float4 wa = *(const float4*)&wrow[cc * 16 + 0];
            float4 wb = *(const float4*)&wrow[cc * 16 + 4];
            float4 wc4 = *(const float4*)&wrow[cc * 16 + 8];
            float4 wd = *(const float4*)&wrow[cc * 16 + 12];
            float wregs[16] = {wa.x, wa.y, wa.z, wa.w, wb.x, wb.y, wb.z, wb.w,
                               wc4.x, wc4.y, wc4.z, wc4.w, wd.x, wd.y, wd.z, wd.w};
            #pragma unroll
            for (int k = 0; k < 16; k++) {
                int c = cc * 16 + k;
                u64 wp = pk(wregs[k], wregs[k]);
                u64 b0 = *(const u64*)&s[c][j0];
                u64 b1 = *(const u64*)&s[c][j0 + 2];
                fma2(acc0, wp, b0);
                fma2(acc1, wp, b1);
            }
        }

        float f0, f1, f2, f3;
        unpk(acc0, f0, f1);
        unpk(acc1, f2, f3);
        if (sel == 0) {
            const float scale = 0.125f;
            g_q[(size_t)(((b << 12) + n0 + j0 + 0) << 6) + o] = __float2bfloat16(f0 * scale);
            g_q[(size_t)(((b << 12) + n0 + j0 + 1) << 6) + o] = __float2bfloat16(f1 * scale);
            g_q[(size_t)(((b << 12) + n0 + j0 + 2) << 6) + o] = __float2bfloat16(f2 * scale);
            g_q[(size_t)(((b << 12) + n0 + j0 + 3) << 6) + o] = __float2bfloat16(f3 * scale);
        } else if (sel == 1) {
            g_kT[(size_t)(((b << 12) + n0 + j0 + 0) << 6) + o] = __float2bfloat16(f0);
            g_kT[(size_t)(((b << 12) + n0 + j0 + 1) << 6) + o] = __float2bfloat16(f1);
            g_kT[(size_t)(((b << 12) + n0 + j0 + 2) << 6) + o] = __float2bfloat16(f2);
            g_kT[(size_t)(((b << 12) + n0 + j0 + 3) << 6) + o] = __float2bfloat16(f3);
        } else {
            uint2 pv;
            pv.x = pack_bf16x2(f1, f0);
            pv.y = pack_bf16x2(f3, f2);
            *(uint2*)&g_v[(size_t)(((b << 6) + o) << 12) + n0 + j0] = pv;
        }
    }
}

// ---------------- kernel 2: S = Q K^T -> bf16, 128n x 512m per CTA, cp.async 2-stage ----------------
__global__ __launch_bounds__(256) void scores_mma()
{
    __shared__ __align__(16) char sQ[128 * 128];       // 16 KB
    __shared__ __align__(16) char sK[2][128 * 128];    // 32 KB
    const int b = blockIdx.z, n0 = blockIdx.y * 128, mB = blockIdx.x * 512;
    const int t = threadIdx.x, wid = t >> 5, lane = t & 31;
    const uint32_t sQb = smem_u32(sQ);
    const uint32_t sKb0 = smem_u32(sK[0]);

    #pragma unroll
    for (int k = 0; k < 4; k++) {
        int i = t + k * 256;
        int r = i >> 3, q = i & 7;
        cp16(sQb + r * 128 + SWZ(r, q * 16),
             &g_q[(size_t)((b << 12) + n0 + r) * 64 + q * 8]);
        cp16(sKb0 + r * 128 + SWZ(r, q * 16),
             &g_kT[(size_t)((b << 12) + mB + r) * 64 + q * 8]);
    }
    CP_COMMIT();

    const int wn = wid >> 2, wm = wid & 3;   // warp tile: 64n x 32m
    const int gid = lane >> 2, tc = lane & 3;

    for (int mi = 0; mi < 4; mi++) {
        const uint32_t sKc = sKb0 + (mi & 1) * 16384;
        if (mi < 3) {
            const uint32_t sKn = sKb0 + ((mi + 1) & 1) * 16384;
            const int m0n = mB + (mi + 1) * 128;
            #pragma unroll
            for (int k = 0; k < 4; k++) {
                int i = t + k * 256;
                int r = i >> 3, q = i & 7;
                cp16(sKn + r * 128 + SWZ(r, q * 16),
                     &g_kT[(size_t)((b << 12) + m0n + r) * 64 + q * 8]);
            }
            CP_COMMIT();
            CP_WAIT(1);
        } else {
            CP_WAIT(0);
        }
        __syncthreads();

        float acc[4][4][4];
        #pragma unroll
        for (int i = 0; i < 4; i++)
            #pragma unroll
            for (int j = 0; j < 4; j++)
                #pragma unroll
                for (int e = 0; e < 4; e++) acc[i][j][e] = 0.f;

        #pragma unroll
        for (int ki = 0; ki < 4; ki++) {
            uint32_t afr[4][4], bfr[4][2];
            #pragma unroll
            for (int i = 0; i < 4; i++) {
                int row = wn * 64 + i * 16 + (lane & 15);
                int cb = ki * 32 + (lane >> 4) * 16;
                ldm_x4(afr[i], sQb + row * 128 + SWZ(row, cb));
            }
            #pragma unroll
            for (int j = 0; j < 4; j++) {
                int row = wm * 32 + j * 8 + (lane & 7);
                int cb = ki * 32 + ((lane >> 3) & 1) * 16;
                ldm_x2(bfr[j], sKc + row * 128 + SWZ(row, cb));
            }
            #pragma unroll
            for (int i = 0; i < 4; i++)
                #pragma unroll
                for (int j = 0; j < 4; j++)
                    mma_bf16(acc[i][j], afr[i], bfr[j]);
        }

        const int m0 = mB + mi * 128;
        #pragma unroll
        for (int i = 0; i < 4; i++) {
            int row = n0 + wn * 64 + i * 16 + gid;
            size_t r0 = ((size_t)b << 24) + (size_t)row * NTOK + m0 + wm * 32;
            size_t r1 = r0 + 8 * NTOK;
            #pragma unroll
            for (int j = 0; j < 4; j++) {
                *(unsigned*)&g_sb[r0 + j * 8 + tc * 2] = pack_bf16x2(acc[i][j][1], acc[i][j][0]);
                *(unsigned*)&g_sb[r1 + j * 8 + tc * 2] = pack_bf16x2(acc[i][j][3], acc[i][j][2]);
            }
        }
        __syncthreads();
    }
}

// ---------------- kernel 3: top-k threshold + masked softmax, fixed-range bins ----------------
__global__ __launch_bounds__(256) void select_softmax_kernel()
{
    const int row = blockIdx.x;
    const int b = row >> 12, n = row & 4095;
    const size_t base = ((size_t)b << 24) + (size_t)n * NTOK;
    const int t = threadIdx.x;
    const int wid = t >> 5, lane = t & 31;

    __shared__ int hist8[8][256];
    __shared__ float candF[4096];
    __shared__ float warpMax[8];
    __shared__ int warpTot[8];
    __shared__ int sh_cnt;
    __shared__ int sh_bin, sh_kk;
    __shared__ float sh_thr, sh_z;

    if (t == 0) { sh_cnt = 0; sh_z = 0.f; }
    #pragma unroll
    for (int w = 0; w < 8; w++) hist8[w][t] = 0;

    float vals[16];
    const size_t myb = base + (size_t)t * 16;
    #pragma unroll
    for (int h = 0; h < 2; h++) {
        uint4 raw = *(const uint4*)&g_sb[myb + h * 8];
        unsigned uw[4] = {raw.x, raw.y, raw.z, raw.w};
        #pragma unroll
        for (int j = 0; j < 4; j++) {
            vals[h * 8 + j * 2 + 0] = __uint_as_float(uw[j] << 16);
            vals[h * 8 + j * 2 + 1] = __uint_as_float(uw[j] & 0xffff0000u);
        }
    }

    float mymax = vals[0];
    #pragma unroll
    for (int i = 1; i < 16; i++) mymax = fmaxf(mymax, vals[i]);
    #pragma unroll
    for (int off = 16; off; off >>= 1)
        mymax = fmaxf(mymax, __shfl_xor_sync(0xffffffffu, mymax, off));
    if (lane == 0) warpMax[wid] = mymax;

    int* myh = hist8[wid];
    int bins[16];
    #pragma unroll
    for (int i = 0; i < 16; i++) {
        int bin = (int)((vals[i] + 8.0f) * 16.0f);   // fixed range [-8, 8] -> 256 bins
        bin = bin < 0 ? 0 : (bin > 255 ? 255 : bin);
        bins[i] = bin;
        atomicAdd(&myh[bin], 1);
    }
    __syncthreads();

    float rmax = warpMax[0];
    #pragma unroll
    for (int w = 1; w < 8; w++) rmax = fmaxf(rmax, warpMax[w]);

    int tot = 0;
    #pragma unroll
    for (int w = 0; w < 8; w++) tot += hist8[w][t];
    int v = tot;
    #pragma unroll
    for (int off = 1; off < 32; off <<= 1) {
        int o = __shfl_down_sync(0xffffffffu, v, off);
        if (lane + off < 32) v += o;
    }
    if (lane == 0) warpTot[wid] = v;
    __syncthreads();
    int above = 0;
    #pragma unroll
    for (int w = 0; w < 8; w++) if (w > wid) above += warpTot[w];
    int cum_incl = v + above, cum_excl = cum_incl - tot;
    if (cum_excl < KSEL && KSEL <= cum_incl) { sh_bin = t; sh_kk = KSEL - cum_excl; }
    __syncthreads();
    const int selbin = sh_bin;
    const int kk = sh_kk;

    {
        int cnt = 0;
        #pragma unroll
        for (int i = 0; i < 16; i++) cnt += (bins[i] == selbin);
        int pos = 0;
        if (cnt) pos = atomicAdd(&sh_cnt, cnt);
        #pragma unroll
        for (int i = 0; i < 16; i++)
            if (bins[i] == selbin) candF[pos++] = vals[i];
    }
    __syncthreads();
    const int ncand = sh_cnt;

    for (int i = t; i < ncand; i += 256) {
        float xx = candF[i];
        int gt = 0, eq = 0;
        for (int j = 0; j < ncand; j++) {
            float y = candF[j];
            gt += (y > xx);
            eq += (y == xx);
        }
        if (gt < kk && kk <= gt + eq) sh_thr = xx;
    }
    __syncthreads();

    const float thr = sh_thr;
    const float M = fmaxf(rmax, 0.f);
    const float expM = __expf(-M);

    float w[16];
    float zloc = 0.f;
    int nkept = 0;
    #pragma unroll
    for (int i = 0; i < 16; i++) {
        if (vals[i] >= thr) {
            float e = __expf(vals[i] - M);
            w[i] = e;
            zloc += e;
            nkept++;
        } else {
            w[i] = expM;
        }
    }
    zloc += (16 - nkept) * expM;
    #pragma unroll
    for (int off = 16; off; off >>= 1) zloc += __shfl_xor_sync(0xffffffffu, zloc, off);
    if (lane == 0) atomicAdd(&sh_z, zloc);
    __syncthreads();

    float invZ = 1.f / sh_z;
    #pragma unroll
    for (int h = 0; h < 2; h++) {
        uint4 o;
        o.x = pack_bf16x2(w[h*8+1] * invZ, w[h*8+0] * invZ);
        o.y = pack_bf16x2(w[h*8+3] * invZ, w[h*8+2] * invZ);
        o.z = pack_bf16x2(w[h*8+5] * invZ, w[h*8+4] * invZ);
        o.w = pack_bf16x2(w[h*8+7] * invZ, w[h*8+6] * invZ);
        *(uint4*)&g_p[myb + h * 8] = o;
    }
}

// ---------------- kernel 4: O(n,c) = P V^T, 64n x 64c per CTA, cp.async 3-stage ----------------
__global__ __launch_bounds__(256) void av_mma()
{
    __shared__ __align__(16) char sP[3][64 * 128];   // 24 KB
    __shared__ __align__(16) char sV[3][64 * 128];   // 24 KB
    const int b = blockIdx.y, n0 = blockIdx.x * 64;
    const int t = threadIdx.x, wid = t >> 5, lane = t & 31;
    const uint32_t sPb0 = smem_u32(sP[0]), sVb0 = smem_u32(sV[0]);
    const size_t pb = ((size_t)b << 24);

    #pragma unroll
    for (int c0 = 0; c0 < 2; c0++) {
        const uint32_t sPn = sPb0 + c0 * 8192;
        const uint32_t sVn = sVb0 + c0 * 8192;
        const int mb = c0 * 64;
        #pragma unroll
        for (int k = 0; k < 2; k++) {
            int i = t + k * 256;
            int r = i >> 3, q = i & 7;
            cp16(sPn + r * 128 + SWZ(r, q * 16),
                 &g_p[pb + (size_t)(n0 + r) * NTOK + mb + q * 8]);
            cp16(sVn + r * 128 + SWZ(r, q * 16),
                 &g_v[(size_t)(((b << 6) + r) << 12) + mb + q * 8]);
        }
        CP_COMMIT();
    }

    const int wn = wid >> 2, wc = wid & 3;   // warp tile: 32n x 16c
    float acc[2][2][4];
    #pragma unroll
    for (int i = 0; i < 2; i++)
        #pragma unroll
        for (int j = 0; j < 2; j++)
            #pragma unroll
            for (int e = 0; e < 4; e++) acc[i][j][e] = 0.f;

    int cur = 0, nxt = 2;
    for (int mt = 0; mt < 64; mt++) {
        if (mt < 62) {
            const int mb = (mt + 2) * 64;
            const uint32_t sPn = sPb0 + nxt * 8192;
            const uint32_t sVn = sVb0 + nxt * 8192;
            #pragma unroll
            for (int k = 0; k < 2; k++) {
                int i = t + k * 256;
                int r = i >> 3, q = i & 7;
                cp16(sPn + r * 128 + SWZ(r, q * 16),
                     &g_p[pb + (size_t)(n0 + r) * NTOK + mb + q * 8]);
                cp16(sVn + r * 128 + SWZ(r, q * 16),
                     &g_v[(size_t)(((b << 6) + r) << 12) + mb + q * 8]);
            }
            CP_COMMIT();
            CP_WAIT(2);
            nxt = nxt + 1 == 3 ? 0 : nxt + 1;
        } else {
            CP_WAIT(0);
        }
        __syncthreads();

        const uint32_t sPc = sPb0 + cur * 8192;
        const uint32_t sVc = sVb0 + cur * 8192;
        #pragma unroll
        for (int ki = 0; ki < 4; ki++) {
            uint32_t afr[2][4], bfr[2][2];
            #pragma unroll
            for (int i = 0; i < 2; i++) {
                int row = wn * 32 + i * 16 + (lane & 15);
                int cb = ki * 32 + (lane >> 4) * 16;
                ldm_x4(afr[i], sPc + row * 128 + SWZ(row, cb));
            }
            #pragma unroll
            for (int j = 0; j < 2; j++) {
                int row = wc * 16 + j * 8 + (lane & 7);
                int cb = ki * 32 + ((lane >> 3) & 1) * 16;
                ldm_x2(bfr[j], sVc + row * 128 + SWZ(row, cb));
            }
            #pragma unroll
            for (int i = 0; i < 2; i++)
                #pragma unroll
                for (int j = 0; j < 2; j++)
                    mma_bf16(acc[i][j], afr[i], bfr[j]);
        }
        __syncthreads();
        cur = cur + 1 == 3 ? 0 : cur + 1;
    }

    const int gid = lane >> 2, tc = lane & 3;
    #pragma unroll
    for (int i = 0; i < 2; i++) {
        int row = n0 + wn * 32 + i * 16 + gid;
        size_t r0 = (size_t)((b << 12) + row) * 64 + wc * 16;
        size_t r1 = r0 + 8 * 64;
        #pragma unroll
        for (int j = 0; j < 2; j++) {
            *(float2*)&g_o[r0 + j * 8 + tc * 2] = make_float2(acc[i][j][0], acc[i][j][1]);
            *(float2*)&g_o[r1 + j * 8 + tc * 2] = make_float2(acc[i][j][2], acc[i][j][3]);
        }
    }
}

// ---------------- kernel 5: output projection + bias + residual, f32x2 quads ----------------
__global__ __launch_bounds__(256) void proj_kernel(const float* __restrict__ x,
                                                   const float* __restrict__ w_out,
                                                   const float* __restrict__ b_out,
                                                   const float* __restrict__ gamma,
                                                   float* __restrict__ out)
{
    __shared__ float sT[64][66];   // pad 66 -> 264B row stride, 8B-aligned LDS.64
    __shared__ float sw[64][64];   // w_out[o][c]
    const int b  = blockIdx.y;
    const int n0 = blockIdx.x * 64;
    const int t  = threadIdx.x;

    for (int idx = t; idx < 64 * 64; idx += 256) {
        int j = idx >> 6, c = idx & 63;
        sT[c][j] = g_o[(size_t)((b << 12) + n0 + j) * 64 + c];
        sw[idx >> 6][idx & 63] = w_out[idx];
    }
    __syncthreads();

    const float g = gamma[0];
    #pragma unroll
    for (int r = 0; r < 4; r++) {
        int qi = t + (r << 8);               // 1024 quads
        int o  = qi >> 4;
        int j0 = (qi & 15) << 2;
        float bias = b_out[o];
        u64 acc0 = pk(bias, bias), acc1 = pk(bias, bias);

        #pragma unroll 16
        for (int c = 0; c < 64; c++) {
            float wv = sw[o][c];
            u64 wp = pk(wv, wv);
            u64 b0 = *(const u64*)&sT[c][j0];
            u64 b1 = *(const u64*)&sT[c][j0 + 2];
            fma2(acc0, wp, b0);
            fma2(acc1, wp, b1);
        }

        float f0, f1, f2, f3;
        unpk(acc0, f0, f1);
        unpk(acc1, f2, f3);
        size_t gi = (size_t)(((b << 6) + o) << 12) + n0 + j0;
        float4 xv = *(const float4*)&x[gi];
        *(float4*)&out[gi] = make_float4(g * f0 + xv.x, g * f1 + xv.y,
                                         g * f2 + xv.z, g * f3 + xv.w);
    }
}

// ---------------- launch ----------------
extern "C" void kernel_launch(void* const* d_in, const int* in_sizes, int n_in,
                              void* d_out, int out_size)
{
    const float* x     = (const float*)d_in[0];
    const float* skip  = (const float*)d_in[1];
    const float* w_qkv = (const float*)d_in[2];
    const float* w_out = (const float*)d_in[3];
    const float* b_out = (const float*)d_in[4];
    const float* gamma = (const float*)d_in[5];
    float* out = (float*)d_out;

    qkv_kernel<<<dim3(64, BATCH), 256>>>(x, skip, w_qkv);
    scores_mma<<<dim3(8, 32, BATCH), 256>>>();
    select_softmax_kernel<<<BATCH * NTOK, 256>>>();
    av_mma<<<dim3(64, BATCH), 256>>>();
    proj_kernel<<<dim3(64, BATCH), 256>>>(x, w_out, b_out, gamma, out);
}